// round 1
// baseline (speedup 1.0000x reference)
#include <cuda_runtime.h>
#include <cuda_bf16.h>
#include <math.h>

#define B_ 32
#define T_ 2048
#define D_ 512
#define U_ 512

#define TM 64
#define TU 64
#define VSTRIDE 516   // 512 + 4 pad: makes Vs[m][k] reads bank-conflict-free

// Scratch (static device globals — allocation-free per harness rules)
__device__ float g_projq[B_ * U_];
__device__ float g_score[B_ * T_];

// ---------------------------------------------------------------------------
// Kernel A: proj_q[b,u] = query[b,:] @ W2[:,u] + b2[u] + b1[u]
// (b1 folded in here so the main kernel epilogue only adds one term)
// ---------------------------------------------------------------------------
__global__ void projq_kernel(const float* __restrict__ query,
                             const float* __restrict__ W2,
                             const float* __restrict__ b1,
                             const float* __restrict__ b2) {
    __shared__ float q[D_];
    int b = blockIdx.x;
    for (int i = threadIdx.x; i < D_; i += blockDim.x) q[i] = query[b * D_ + i];
    __syncthreads();
    int u = threadIdx.x;  // 512 threads, one u each
    float acc = b1[u] + b2[u];
#pragma unroll 8
    for (int d = 0; d < D_; d++) acc += q[d] * W2[d * U_ + u];
    g_projq[b * U_ + u] = acc;
}

// ---------------------------------------------------------------------------
// Kernel B: fused  score[row] = sum_u tanh( values[row,:]@W1[:,u] + pq[b,u] ) * V[u]
// Block: 64 rows x full U. values tile resident in smem; W1 slabs (32k x 64u)
// double-buffered. 256 threads, 4x4 microtile each.
// ---------------------------------------------------------------------------
__global__ void __launch_bounds__(256)
score_kernel(const float* __restrict__ values,
             const float* __restrict__ W1,
             const float* __restrict__ V) {
    extern __shared__ float smem[];
    float* Vs  = smem;                       // 64 * 516
    float* Ws  = smem + TM * VSTRIDE;        // 2 * 32 * 64 (double buffer)
    float* red = Ws + 2 * 32 * TU;           // 64 * 16

    const int tid = threadIdx.x;
    const int tx = tid & 15;                 // u group (4 u's each)
    const int ty = tid >> 4;                 // m group (4 m's each)
    const int row0 = blockIdx.x * TM;        // tile stays inside one batch (2048 % 64 == 0)
    const int b = row0 / T_;

    // Load values tile [64 x 512] -> smem (source is contiguous; dest row-padded)
    {
        const float4* src4 = (const float4*)(values + (size_t)row0 * D_);
        float4* Vs4 = (float4*)Vs;           // VSTRIDE*4 bytes divisible by 16
#pragma unroll
        for (int i = 0; i < 32; i++) {
            int idx = tid + i * 256;         // 8192 float4 total
            int r = idx >> 7, c = idx & 127;
            Vs4[r * 129 + c] = src4[idx];
        }
    }

    float score_acc[4] = {0.f, 0.f, 0.f, 0.f};

    const int id0 = tid, id1 = tid + 256;
    const int r0 = id0 >> 4, c0 = id0 & 15;
    const int r1 = id1 >> 4, c1 = id1 & 15;

    for (int ut = 0; ut < U_ / TU; ut++) {
        const int u0 = ut * TU;
        float acc[4][4];
#pragma unroll
        for (int i = 0; i < 4; i++)
#pragma unroll
            for (int j = 0; j < 4; j++) acc[i][j] = 0.f;

        // preload slab 0 into buffer 0
        {
            float4 p0 = *(const float4*)(W1 + (size_t)r0 * U_ + u0 + c0 * 4);
            float4 p1 = *(const float4*)(W1 + (size_t)r1 * U_ + u0 + c1 * 4);
            *(float4*)(Ws + r0 * TU + c0 * 4) = p0;
            *(float4*)(Ws + r1 * TU + c1 * 4) = p1;
        }
        __syncthreads();

        for (int ks = 0; ks < 16; ks++) {
            float4 p0, p1;
            if (ks < 15) {                   // prefetch next slab from global
                int kk = (ks + 1) * 32;
                p0 = *(const float4*)(W1 + (size_t)(kk + r0) * U_ + u0 + c0 * 4);
                p1 = *(const float4*)(W1 + (size_t)(kk + r1) * U_ + u0 + c1 * 4);
            }
            const float* Wb = Ws + (ks & 1) * (32 * TU);
            const int kbase = ks * 32;
#pragma unroll
            for (int k = 0; k < 32; k++) {
                float4 w4 = *(const float4*)(Wb + k * TU + tx * 4);
                float a[4];
#pragma unroll
                for (int i = 0; i < 4; i++)
                    a[i] = Vs[(ty * 4 + i) * VSTRIDE + kbase + k];
#pragma unroll
                for (int i = 0; i < 4; i++) {
                    acc[i][0] += a[i] * w4.x;
                    acc[i][1] += a[i] * w4.y;
                    acc[i][2] += a[i] * w4.z;
                    acc[i][3] += a[i] * w4.w;
                }
            }
            if (ks < 15) {                   // stage prefetched slab
                float* Wn = Ws + ((ks + 1) & 1) * (32 * TU);
                *(float4*)(Wn + r0 * TU + c0 * 4) = p0;
                *(float4*)(Wn + r1 * TU + c1 * 4) = p1;
            }
            __syncthreads();
        }

        // epilogue for this u-tile: tanh + dot with V
        float4 pq = *(const float4*)(g_projq + b * U_ + u0 + tx * 4);
        float4 vv = *(const float4*)(V + u0 + tx * 4);
#pragma unroll
        for (int i = 0; i < 4; i++) {
            score_acc[i] += tanhf(acc[i][0] + pq.x) * vv.x
                          + tanhf(acc[i][1] + pq.y) * vv.y
                          + tanhf(acc[i][2] + pq.z) * vv.z
                          + tanhf(acc[i][3] + pq.w) * vv.w;
        }
    }

    // reduce partial scores over the 16 tx lanes
#pragma unroll
    for (int i = 0; i < 4; i++) red[(ty * 4 + i) * 16 + tx] = score_acc[i];
    __syncthreads();
    if (tid < TM) {
        float s = 0.f;
#pragma unroll
        for (int j = 0; j < 16; j++) s += red[tid * 16 + j];
        g_score[row0 + tid] = s;
    }
}

// ---------------------------------------------------------------------------
// Kernel C: softmax over T per batch; writes attention weights to the output
// tail; also zeroes the context region (for kernel D's atomics).
// ---------------------------------------------------------------------------
__global__ void softmax_kernel(float* __restrict__ out) {
    __shared__ float sdata[256];
    const int b = blockIdx.x, tid = threadIdx.x;
    float s[8];
    float mx = -1e30f;
#pragma unroll
    for (int i = 0; i < 8; i++) {
        s[i] = g_score[b * T_ + tid + i * 256];
        mx = fmaxf(mx, s[i]);
    }
    sdata[tid] = mx;
    __syncthreads();
    for (int off = 128; off > 0; off >>= 1) {
        if (tid < off) sdata[tid] = fmaxf(sdata[tid], sdata[tid + off]);
        __syncthreads();
    }
    mx = sdata[0];
    __syncthreads();
    float sum = 0.f;
#pragma unroll
    for (int i = 0; i < 8; i++) {
        s[i] = __expf(s[i] - mx);
        sum += s[i];
    }
    sdata[tid] = sum;
    __syncthreads();
    for (int off = 128; off > 0; off >>= 1) {
        if (tid < off) sdata[tid] += sdata[tid + off];
        __syncthreads();
    }
    float inv = 1.0f / sdata[0];
    float* w = out + B_ * D_;  // weights region after context
#pragma unroll
    for (int i = 0; i < 8; i++) w[b * T_ + tid + i * 256] = s[i] * inv;

    // zero context region for kernel D
    out[b * D_ + tid] = 0.f;
    out[b * D_ + 256 + tid] = 0.f;
}

// ---------------------------------------------------------------------------
// Kernel D: context[b,d] = sum_t w[b,t] * values[b,t,d]
// grid (32 b, 8 t-chunks), 256 threads (2 d's each), fp32 atomics into out.
// ---------------------------------------------------------------------------
__global__ void context_kernel(const float* __restrict__ values,
                               float* __restrict__ out) {
    const int b = blockIdx.x;
    const int t0 = blockIdx.y * 256;
    const int tid = threadIdx.x;
    __shared__ float ws[256];
    const float* w = out + B_ * D_ + b * T_ + t0;
    ws[tid] = w[tid];
    __syncthreads();
    const float* vp = values + ((size_t)b * T_ + t0) * D_ + tid;
    float a0 = 0.f, a1 = 0.f;
#pragma unroll 4
    for (int tt = 0; tt < 256; tt++) {
        float wt = ws[tt];
        a0 += wt * vp[0];
        a1 += wt * vp[256];
        vp += D_;
    }
    atomicAdd(&out[b * D_ + tid], a0);
    atomicAdd(&out[b * D_ + tid + 256], a1);
}

// ---------------------------------------------------------------------------
extern "C" void kernel_launch(void* const* d_in, const int* in_sizes, int n_in,
                              void* d_out, int out_size) {
    const float* values = (const float*)d_in[0];  // [B,T,D]
    const float* query  = (const float*)d_in[1];  // [B,D]
    const float* W1     = (const float*)d_in[2];  // [D,U]
    const float* b1     = (const float*)d_in[3];  // [U]
    const float* W2     = (const float*)d_in[4];  // [D,U]
    const float* b2     = (const float*)d_in[5];  // [U]
    const float* V      = (const float*)d_in[6];  // [U,1]
    // d_in[7] = bV: softmax is shift-invariant -> unused
    float* out = (float*)d_out;  // [B*D context | B*T weights]

    const int smem_bytes = (TM * VSTRIDE + 2 * 32 * TU + TM * 16) * sizeof(float);
    cudaFuncSetAttribute(score_kernel,
                         cudaFuncAttributeMaxDynamicSharedMemorySize, smem_bytes);

    projq_kernel<<<B_, 512>>>(query, W2, b1, b2);
    score_kernel<<<(B_ * T_) / TM, 256, smem_bytes>>>(values, W1, V);
    softmax_kernel<<<B_, 256>>>(out);
    context_kernel<<<dim3(B_, 8), 256>>>(values, out);
}

// round 3
// speedup vs baseline: 2.2487x; 2.2487x over previous
#include <cuda_runtime.h>
#include <cuda_bf16.h>
#include <math.h>
#include <stdint.h>

#define B_ 32
#define T_ 2048
#define D_ 512
#define U_ 512

// ---------------------------------------------------------------------------
// score-kernel tiling
// ---------------------------------------------------------------------------
#define MT 64                 // rows per CTA
#define NTILE 64              // u per N-tile (8 tiles)
#define KCH 128               // k per B chunk (4 chunks)
#define A_STRIDE_B 1040       // bytes per A row (520 bf16: pad -> conflict-free)
#define B_STRIDE_B 272        // bytes per B row (136 bf16)

// smem byte offsets (dynamic smem)
#define SM_A_HI   0
#define SM_A_LO   66560                   // 64*1040
#define SM_B      133120                  // 2 bufs x (hi 17408 + lo 17408)
#define SM_B_BUF  34816
#define SM_B_LO   17408
#define SM_PQ     202752
#define SM_V      204800
#define SM_RED    206848                  // 64 rows x 4 wn x f32
#define SMEM_TOTAL 207872

// ---------------------------------------------------------------------------
// scratch globals
// ---------------------------------------------------------------------------
__device__ float g_projq[B_ * U_];
__device__ float g_score[B_ * T_];
__device__ __align__(16) __nv_bfloat16 g_W1t_hi[U_ * D_];  // [n][k]
__device__ __align__(16) __nv_bfloat16 g_W1t_lo[U_ * D_];

// ---------------------------------------------------------------------------
// PTX helpers (all sm_80+; no 'a' features)
// ---------------------------------------------------------------------------
__device__ __forceinline__ uint32_t smem_u32(const void* p) {
    uint32_t a;
    asm("{ .reg .u64 t; cvta.to.shared.u64 t, %1; cvt.u32.u64 %0, t; }"
        : "=r"(a) : "l"(p));
    return a;
}
__device__ __forceinline__ void cp_async16(uint32_t dst, const void* src) {
    asm volatile("cp.async.cg.shared.global [%0], [%1], 16;"
                 :: "r"(dst), "l"(src) : "memory");
}
#define CP_COMMIT() asm volatile("cp.async.commit_group;" ::: "memory")
#define CP_WAIT(n)  asm volatile("cp.async.wait_group %0;" :: "n"(n) : "memory")

__device__ __forceinline__ void ldsm4(uint32_t* r, uint32_t addr) {
    asm volatile("ldmatrix.sync.aligned.m8n8.x4.shared.b16 {%0,%1,%2,%3}, [%4];"
                 : "=r"(r[0]), "=r"(r[1]), "=r"(r[2]), "=r"(r[3]) : "r"(addr));
}
__device__ __forceinline__ void ldsm2(uint32_t* r, uint32_t addr) {
    asm volatile("ldmatrix.sync.aligned.m8n8.x2.shared.b16 {%0,%1}, [%2];"
                 : "=r"(r[0]), "=r"(r[1]) : "r"(addr));
}
__device__ __forceinline__ void mma_bf16(float* d, const uint32_t* a, const uint32_t* b) {
    asm volatile(
        "mma.sync.aligned.m16n8k16.row.col.f32.bf16.bf16.f32 "
        "{%0,%1,%2,%3}, {%4,%5,%6,%7}, {%8,%9}, {%0,%1,%2,%3};"
        : "+f"(d[0]), "+f"(d[1]), "+f"(d[2]), "+f"(d[3])
        : "r"(a[0]), "r"(a[1]), "r"(a[2]), "r"(a[3]), "r"(b[0]), "r"(b[1]));
}

__device__ __forceinline__ float tanh_fast(float x) {
    float xc = fminf(fmaxf(x, -9.0f), 9.0f);
    float e = __expf(2.0f * xc);
    return (e - 1.0f) / (e + 1.0f);
}

// ---------------------------------------------------------------------------
// W1 transpose + bf16 hi/lo split:  W1[k][n] -> W1t_{hi,lo}[n][k]
// ---------------------------------------------------------------------------
__global__ void w1split_kernel(const float* __restrict__ W1) {
    int k = blockIdx.x;
    int n = threadIdx.x;
    float x = W1[k * U_ + n];
    __nv_bfloat16 h = __float2bfloat16(x);
    __nv_bfloat16 l = __float2bfloat16(x - __bfloat162float(h));
    g_W1t_hi[n * D_ + k] = h;
    g_W1t_lo[n * D_ + k] = l;
}

// ---------------------------------------------------------------------------
// proj_q[b,u] = query[b,:] @ W2[:,u] + b2[u] + b1[u]
// ---------------------------------------------------------------------------
__global__ void projq_kernel(const float* __restrict__ query,
                             const float* __restrict__ W2,
                             const float* __restrict__ b1,
                             const float* __restrict__ b2) {
    __shared__ float q[D_];
    int b = blockIdx.x;
    for (int i = threadIdx.x; i < D_; i += blockDim.x) q[i] = query[b * D_ + i];
    __syncthreads();
    int u = threadIdx.x;
    float acc = b1[u] + b2[u];
#pragma unroll 8
    for (int d = 0; d < D_; d++) acc += q[d] * W2[d * U_ + u];
    g_projq[b * U_ + u] = acc;
}

// ---------------------------------------------------------------------------
// score kernel: mma.sync split-bf16 GEMM + fused tanh/V epilogue
// CTA: 64 rows, 8 warps (2M x 4N), warp tile 32x16, N-tiles of 64 u
// ---------------------------------------------------------------------------
__global__ void __launch_bounds__(256, 1)
score_kernel(const float* __restrict__ values, const float* __restrict__ V) {
    extern __shared__ char smem[];
    const uint32_t sb = smem_u32(smem);
    const int tid = threadIdx.x;
    const int wid = tid >> 5;
    const int lane = tid & 31;
    const int wm = wid & 1;           // 0..1 (32-row groups)
    const int wn = wid >> 1;          // 0..3 (16-u groups)
    const int row0 = blockIdx.x * MT;
    const int b = row0 / T_;

    // ---- preload B chunk 0 via cp.async ----
    {
#pragma unroll
        for (int it = 0; it < 4; it++) {
            int idx = tid + it * 256;           // 1024 16B-chunks per split
            int n = idx >> 4, c = idx & 15;
            uint32_t dst = sb + SM_B + n * B_STRIDE_B + c * 16;
            size_t goff = (size_t)n * D_ + c * 8;
            cp_async16(dst, g_W1t_hi + goff);
            cp_async16(dst + SM_B_LO, g_W1t_lo + goff);
        }
        CP_COMMIT();
    }

    // ---- stage pq + V ----
    {
        float* pqs = (float*)(smem + SM_PQ);
        float* Vs = (float*)(smem + SM_V);
        for (int i = tid; i < U_; i += 256) {
            pqs[i] = g_projq[b * U_ + i];
            Vs[i] = V[i];
        }
    }

    // ---- convert A (values[64 x 512]) fp32 -> bf16 hi/lo into smem ----
    {
        const float4* src = (const float4*)(values + (size_t)row0 * D_);
#pragma unroll
        for (int it = 0; it < 32; it++) {
            int idx = tid + it * 256;           // 8192 float4
            int r = idx >> 7, c = idx & 127;    // 128 float4 per row
            float4 v = src[idx];
            __nv_bfloat16 h0 = __float2bfloat16(v.x);
            __nv_bfloat16 h1 = __float2bfloat16(v.y);
            __nv_bfloat16 h2 = __float2bfloat16(v.z);
            __nv_bfloat16 h3 = __float2bfloat16(v.w);
            __nv_bfloat16 l0 = __float2bfloat16(v.x - __bfloat162float(h0));
            __nv_bfloat16 l1 = __float2bfloat16(v.y - __bfloat162float(h1));
            __nv_bfloat16 l2 = __float2bfloat16(v.z - __bfloat162float(h2));
            __nv_bfloat16 l3 = __float2bfloat16(v.w - __bfloat162float(h3));
            uint32_t hp0 = ((uint32_t)__bfloat16_as_ushort(h1) << 16) | __bfloat16_as_ushort(h0);
            uint32_t hp1 = ((uint32_t)__bfloat16_as_ushort(h3) << 16) | __bfloat16_as_ushort(h2);
            uint32_t lp0 = ((uint32_t)__bfloat16_as_ushort(l1) << 16) | __bfloat16_as_ushort(l0);
            uint32_t lp1 = ((uint32_t)__bfloat16_as_ushort(l3) << 16) | __bfloat16_as_ushort(l2);
            uint32_t off = r * A_STRIDE_B + c * 8;
            *(uint2*)(smem + SM_A_HI + off) = make_uint2(hp0, hp1);
            *(uint2*)(smem + SM_A_LO + off) = make_uint2(lp0, lp1);
        }
    }

    // ---- per-lane ldmatrix base addresses ----
    // A (x4): lanes 0-7 rows r0..7 @k0 | 8-15 rows 8..15 @k0 | 16-23 rows 0..7 @k+8 | 24-31 rows 8..15 @k+8
    const uint32_t a_lane = (uint32_t)(((lane & 7) + ((lane >> 3) & 1) * 8) * A_STRIDE_B
                                       + (lane >> 4) * 16);
    const uint32_t a_base = sb + SM_A_HI + (uint32_t)(wm * 32) * A_STRIDE_B + a_lane;
    // B (x2): lanes 0-7 rows n0..7 @k0 | 8-15 rows n0..7 @k+8
    const uint32_t b_lane = (uint32_t)((lane & 7) * B_STRIDE_B + ((lane >> 3) & 1) * 16);
    const uint32_t b_base = sb + SM_B + (uint32_t)(wn * 16) * B_STRIDE_B + b_lane;

    float acc[2][2][4];
#pragma unroll
    for (int mf = 0; mf < 2; mf++)
#pragma unroll
        for (int nf = 0; nf < 2; nf++)
#pragma unroll
            for (int j = 0; j < 4; j++) acc[mf][nf][j] = 0.f;
    float sp[4] = {0.f, 0.f, 0.f, 0.f};

    const float* pqs = (const float*)(smem + SM_PQ);
    const float* Vs = (const float*)(smem + SM_V);

    for (int i = 0; i < 32; i++) {              // (nt, kc) linearized
        const int nt = i >> 2;
        const int kc = i & 3;
        const int buf = i & 1;

        if (i + 1 < 32) {                       // prefetch next chunk
            const int nn = (i + 1) >> 2, nk = (i + 1) & 3, nb = (i + 1) & 1;
#pragma unroll
            for (int it = 0; it < 4; it++) {
                int idx = tid + it * 256;
                int n = idx >> 4, c = idx & 15;
                uint32_t dst = sb + SM_B + nb * SM_B_BUF + n * B_STRIDE_B + c * 16;
                size_t goff = (size_t)(nn * NTILE + n) * D_ + nk * KCH + c * 8;
                cp_async16(dst, g_W1t_hi + goff);
                cp_async16(dst + SM_B_LO, g_W1t_lo + goff);
            }
            CP_COMMIT();
            CP_WAIT(1);
        } else {
            CP_WAIT(0);
        }
        __syncthreads();

        // ---- compute this chunk: 8 ksteps of 16 ----
        const uint32_t ab = a_base + (uint32_t)kc * 256;   // 128 elems * 2B
        const uint32_t bb = b_base + (uint32_t)buf * SM_B_BUF;
#pragma unroll
        for (int ks = 0; ks < 8; ks++) {
            uint32_t ah[2][4], al[2][4], bh[2][2], bl[2][2];
            ldsm4(ah[0], ab + ks * 32);
            ldsm4(ah[1], ab + 16 * A_STRIDE_B + ks * 32);
            ldsm4(al[0], ab + SM_A_LO + ks * 32);
            ldsm4(al[1], ab + SM_A_LO + 16 * A_STRIDE_B + ks * 32);
            ldsm2(bh[0], bb + ks * 32);
            ldsm2(bh[1], bb + 8 * B_STRIDE_B + ks * 32);
            ldsm2(bl[0], bb + SM_B_LO + ks * 32);
            ldsm2(bl[1], bb + SM_B_LO + 8 * B_STRIDE_B + ks * 32);
#pragma unroll
            for (int mf = 0; mf < 2; mf++)
#pragma unroll
                for (int nf = 0; nf < 2; nf++) {
                    mma_bf16(acc[mf][nf], ah[mf], bh[nf]);
                    mma_bf16(acc[mf][nf], ah[mf], bl[nf]);
                    mma_bf16(acc[mf][nf], al[mf], bh[nf]);
                }
        }

        if (kc == 3) {
            // ---- epilogue for N-tile nt: tanh(acc + pq) * V ----
#pragma unroll
            for (int mf = 0; mf < 2; mf++)
#pragma unroll
                for (int nf = 0; nf < 2; nf++) {
                    int u0 = nt * NTILE + wn * 16 + nf * 8 + (lane & 3) * 2;
                    float pq0 = pqs[u0], pq1 = pqs[u0 + 1];
                    float v0 = Vs[u0], v1 = Vs[u0 + 1];
                    sp[mf * 2 + 0] += tanh_fast(acc[mf][nf][0] + pq0) * v0
                                    + tanh_fast(acc[mf][nf][1] + pq1) * v1;
                    sp[mf * 2 + 1] += tanh_fast(acc[mf][nf][2] + pq0) * v0
                                    + tanh_fast(acc[mf][nf][3] + pq1) * v1;
#pragma unroll
                    for (int j = 0; j < 4; j++) acc[mf][nf][j] = 0.f;
                }
        }
        __syncthreads();                        // protect buffer reuse
    }

    // ---- reduce score partials ----
#pragma unroll
    for (int j = 0; j < 4; j++) {
        sp[j] += __shfl_xor_sync(0xffffffffu, sp[j], 1);
        sp[j] += __shfl_xor_sync(0xffffffffu, sp[j], 2);
    }
    float* red = (float*)(smem + SM_RED);
    if ((lane & 3) == 0) {
        int g = lane >> 2;                      // 0..7
#pragma unroll
        for (int mf = 0; mf < 2; mf++) {
            int r0 = wm * 32 + mf * 16 + g;
            red[r0 * 4 + wn] = sp[mf * 2 + 0];
            red[(r0 + 8) * 4 + wn] = sp[mf * 2 + 1];
        }
    }
    __syncthreads();
    if (tid < MT) {
        g_score[row0 + tid] = red[tid * 4] + red[tid * 4 + 1]
                            + red[tid * 4 + 2] + red[tid * 4 + 3];
    }
}

// Fix: the two writes per mf above land on different rows (r0, r0+8) — but both
// use sp[mf*2+{0,1}] where index 0 is rows g (c0/c1) and 1 is rows g+8 (c2/c3).
// (Layout: c0,c1 -> row groupID; c2,c3 -> row groupID+8.)  Mapping verified.

// ---------------------------------------------------------------------------
// softmax over T per batch -> weights; zero context region
// ---------------------------------------------------------------------------
__global__ void softmax_kernel(float* __restrict__ out) {
    __shared__ float sdata[256];
    const int b = blockIdx.x, tid = threadIdx.x;
    float s[8];
    float mx = -1e30f;
#pragma unroll
    for (int i = 0; i < 8; i++) {
        s[i] = g_score[b * T_ + tid + i * 256];
        mx = fmaxf(mx, s[i]);
    }
    sdata[tid] = mx;
    __syncthreads();
    for (int off = 128; off > 0; off >>= 1) {
        if (tid < off) sdata[tid] = fmaxf(sdata[tid], sdata[tid + off]);
        __syncthreads();
    }
    mx = sdata[0];
    __syncthreads();
    float sum = 0.f;
#pragma unroll
    for (int i = 0; i < 8; i++) {
        s[i] = __expf(s[i] - mx);
        sum += s[i];
    }
    sdata[tid] = sum;
    __syncthreads();
    for (int off = 128; off > 0; off >>= 1) {
        if (tid < off) sdata[tid] += sdata[tid + off];
        __syncthreads();
    }
    float inv = 1.0f / sdata[0];
    float* w = out + B_ * D_;
#pragma unroll
    for (int i = 0; i < 8; i++) w[b * T_ + tid + i * 256] = s[i] * inv;

    out[b * D_ + tid] = 0.f;
    out[b * D_ + 256 + tid] = 0.f;
}

// ---------------------------------------------------------------------------
// context[b,d] = sum_t w[b,t] * values[b,t,d]
// grid (32, 16) x 128 threads; block covers 128 t, each thread 4 d via float4
// ---------------------------------------------------------------------------
__global__ void __launch_bounds__(128)
context_kernel(const float* __restrict__ values, float* __restrict__ out) {
    const int b = blockIdx.x;
    const int t0 = blockIdx.y * 128;
    const int tid = threadIdx.x;
    __shared__ float ws[128];
    ws[tid] = out[B_ * D_ + b * T_ + t0 + tid];
    __syncthreads();
    const float4* vp = (const float4*)(values + ((size_t)b * T_ + t0) * D_) + tid;
    float ax = 0.f, ay = 0.f, az = 0.f, aw = 0.f;
#pragma unroll 4
    for (int tt = 0; tt < 128; tt++) {
        float w = ws[tt];
        float4 v = vp[tt * 128];
        ax += w * v.x; ay += w * v.y; az += w * v.z; aw += w * v.w;
    }
    float* o = out + b * D_ + tid * 4;
    atomicAdd(o + 0, ax);
    atomicAdd(o + 1, ay);
    atomicAdd(o + 2, az);
    atomicAdd(o + 3, aw);
}

// ---------------------------------------------------------------------------
extern "C" void kernel_launch(void* const* d_in, const int* in_sizes, int n_in,
                              void* d_out, int out_size) {
    const float* values = (const float*)d_in[0];  // [B,T,D]
    const float* query  = (const float*)d_in[1];  // [B,D]
    const float* W1     = (const float*)d_in[2];  // [D,U]
    const float* b1     = (const float*)d_in[3];  // [U]
    const float* W2     = (const float*)d_in[4];  // [D,U]
    const float* b2     = (const float*)d_in[5];  // [U]
    const float* V      = (const float*)d_in[6];  // [U,1]
    // d_in[7] = bV: softmax shift-invariant -> unused
    float* out = (float*)d_out;                   // [B*D context | B*T weights]

    cudaFuncSetAttribute(score_kernel,
                         cudaFuncAttributeMaxDynamicSharedMemorySize, SMEM_TOTAL);

    w1split_kernel<<<D_, U_>>>(W1);
    projq_kernel<<<B_, U_>>>(query, W2, b1, b2);
    score_kernel<<<(B_ * T_) / MT, 256, SMEM_TOTAL>>>(values, V);
    softmax_kernel<<<B_, 256>>>(out);
    context_kernel<<<dim3(B_, 16), 128>>>(values, out);
}